// round 3
// baseline (speedup 1.0000x reference)
#include <cuda_runtime.h>
#include <math.h>

// GPT-2 small forward: B=2, T=1024, E=768, H=12, hd=64, L=8, V=50257
#define BATCH 2
#define SEQ   1024
#define EMB   768
#define NH    12
#define HD    64
#define NL    8
#define VOCAB 50257
#define MROWS (BATCH*SEQ)   // 2048

// ---------------- scratch (device globals: alloc-free) ----------------
__device__ float g_x   [MROWS * EMB];        // residual stream
__device__ float g_h   [MROWS * EMB];        // layernorm output
__device__ float g_qkv [MROWS * 3 * EMB];    // qkv projection
__device__ float g_y   [MROWS * EMB];        // attention output
__device__ float g_act [MROWS * 4 * EMB];    // mlp hidden

// ---------------- embedding ----------------
__global__ void embed_kernel(const int* __restrict__ idx,
                             const float* __restrict__ wte,
                             const float* __restrict__ wpe,
                             float* __restrict__ x)
{
    int i = blockIdx.x * blockDim.x + threadIdx.x;
    if (i < MROWS * EMB) {
        int row = i / EMB;
        int e   = i - row * EMB;
        int t   = row % SEQ;
        x[i] = wte[(size_t)idx[row] * EMB + e] + wpe[(size_t)t * EMB + e];
    }
}

// ---------------- layernorm (one block per row) ----------------
__global__ __launch_bounds__(256) void layernorm_kernel(
    const float* __restrict__ x, const float* __restrict__ g,
    const float* __restrict__ b, float* __restrict__ out)
{
    int row = blockIdx.x;
    int tid = threadIdx.x;
    const float* xr = x + (size_t)row * EMB;

    float s = 0.f, ss = 0.f;
    for (int e = tid; e < EMB; e += 256) {
        float v = xr[e];
        s += v; ss += v * v;
    }
    #pragma unroll
    for (int o = 16; o > 0; o >>= 1) {
        s  += __shfl_xor_sync(0xffffffffu, s,  o);
        ss += __shfl_xor_sync(0xffffffffu, ss, o);
    }
    __shared__ float rs[8], rss[8];
    if ((tid & 31) == 0) { rs[tid >> 5] = s; rss[tid >> 5] = ss; }
    __syncthreads();
    __shared__ float smean, sinv;
    if (tid == 0) {
        float S = 0.f, SS = 0.f;
        #pragma unroll
        for (int w = 0; w < 8; w++) { S += rs[w]; SS += rss[w]; }
        float mean = S * (1.0f / EMB);
        float var  = SS * (1.0f / EMB) - mean * mean;
        smean = mean;
        sinv  = rsqrtf(var + 1e-5f);
    }
    __syncthreads();
    float mean = smean, inv = sinv;
    float* orow = out + (size_t)row * EMB;
    for (int e = tid; e < EMB; e += 256)
        orow[e] = (xr[e] - mean) * inv * g[e] + b[e];
}

// ---------------- GEMM: C = A[M,K] @ B[K,N] (+bias)(+gelu)(+resid into C) ----------------
__device__ __forceinline__ float gelu_tanh(float v) {
    float c = v + 0.044715f * v * v * v;
    return 0.5f * v * (1.0f + tanhf(0.7978845608028654f * c));
}

// 128x128 tile, BK=8, 256 threads, 8x8 register tile, 2-stage smem double buffer.
template<bool GELU, bool RESID, bool BIAS>
__global__ __launch_bounds__(256) void gemm_kernel(
    const float* __restrict__ A, const float* __restrict__ B,
    const float* __restrict__ bias, float* __restrict__ C,
    int M, int N, int K)
{
    const int BM = 128, BN = 128, BK = 8;
    __shared__ float As[2][BK][BM];
    __shared__ float Bs[2][BK][BN];

    int bm = blockIdx.y * BM, bn = blockIdx.x * BN;
    int tid = threadIdx.x;

    // A tile loaders: 128 rows x 8 cols, float4 along K
    int arow = tid >> 1, acol = (tid & 1) * 4;
    // B tile loaders: 8 rows x 128 cols, float4 along N
    int brow = tid >> 5, bcol = (tid & 31) * 4;

    bool nvec = ((bn + BN) <= N) && ((N & 3) == 0);  // full N-tile, vector-safe

    int tx = tid & 15, ty = tid >> 4;
    float acc[8][8];
    #pragma unroll
    for (int i = 0; i < 8; i++)
        #pragma unroll
        for (int j = 0; j < 8; j++) acc[i][j] = 0.f;

    const float* Aptr = A + (size_t)(bm + arow) * K + acol;
    const float* Bptr = B + (size_t)brow * N + bn + bcol;

    // ---- load tile 0 into stage 0 ----
    float4 av = *(const float4*)(Aptr);
    float4 bv;
    if (nvec) {
        bv = *(const float4*)(Bptr);
    } else {
        bv.x = (bn + bcol + 0 < N) ? Bptr[0] : 0.f;
        bv.y = (bn + bcol + 1 < N) ? Bptr[1] : 0.f;
        bv.z = (bn + bcol + 2 < N) ? Bptr[2] : 0.f;
        bv.w = (bn + bcol + 3 < N) ? Bptr[3] : 0.f;
    }
    As[0][acol + 0][arow] = av.x;
    As[0][acol + 1][arow] = av.y;
    As[0][acol + 2][arow] = av.z;
    As[0][acol + 3][arow] = av.w;
    *(float4*)&Bs[0][brow][bcol] = bv;
    __syncthreads();

    int stage = 0;
    for (int k0 = 0; k0 < K; k0 += BK) {
        int kn = k0 + BK;
        bool more = kn < K;

        // ---- prefetch next tile into registers (global loads overlap compute) ----
        if (more) {
            av = *(const float4*)(Aptr + kn);
            const float* Bp = Bptr + (size_t)kn * N;
            if (nvec) {
                bv = *(const float4*)Bp;
            } else {
                bv.x = (bn + bcol + 0 < N) ? Bp[0] : 0.f;
                bv.y = (bn + bcol + 1 < N) ? Bp[1] : 0.f;
                bv.z = (bn + bcol + 2 < N) ? Bp[2] : 0.f;
                bv.w = (bn + bcol + 3 < N) ? Bp[3] : 0.f;
            }
        }

        // ---- compute on current stage ----
        #pragma unroll
        for (int kk = 0; kk < BK; kk++) {
            float4 a0 = *(const float4*)&As[stage][kk][ty * 8];
            float4 a1 = *(const float4*)&As[stage][kk][ty * 8 + 4];
            float4 b0 = *(const float4*)&Bs[stage][kk][tx * 8];
            float4 b1 = *(const float4*)&Bs[stage][kk][tx * 8 + 4];
            float a[8] = {a0.x, a0.y, a0.z, a0.w, a1.x, a1.y, a1.z, a1.w};
            float bb[8] = {b0.x, b0.y, b0.z, b0.w, b1.x, b1.y, b1.z, b1.w};
            #pragma unroll
            for (int i = 0; i < 8; i++)
                #pragma unroll
                for (int j = 0; j < 8; j++)
                    acc[i][j] = fmaf(a[i], bb[j], acc[i][j]);
        }

        // ---- store prefetched tile into other stage ----
        if (more) {
            int ns = stage ^ 1;
            As[ns][acol + 0][arow] = av.x;
            As[ns][acol + 1][arow] = av.y;
            As[ns][acol + 2][arow] = av.z;
            As[ns][acol + 3][arow] = av.w;
            *(float4*)&Bs[ns][brow][bcol] = bv;
            __syncthreads();
            stage = ns;
        }
    }

    // ---- epilogue ----
    if (nvec) {
        // vectorized: 2 float4 spans of columns per row
        #pragma unroll
        for (int i = 0; i < 8; i++) {
            int row = bm + ty * 8 + i;
            #pragma unroll
            for (int jv = 0; jv < 2; jv++) {
                int col = bn + tx * 8 + jv * 4;
                float4 v = make_float4(acc[i][jv*4+0], acc[i][jv*4+1],
                                       acc[i][jv*4+2], acc[i][jv*4+3]);
                if (BIAS) {
                    float4 bsv = *(const float4*)(bias + col);
                    v.x += bsv.x; v.y += bsv.y; v.z += bsv.z; v.w += bsv.w;
                }
                if (GELU) {
                    v.x = gelu_tanh(v.x); v.y = gelu_tanh(v.y);
                    v.z = gelu_tanh(v.z); v.w = gelu_tanh(v.w);
                }
                float4* optr = (float4*)(C + (size_t)row * N + col);
                if (RESID) {
                    float4 r = *optr;
                    v.x += r.x; v.y += r.y; v.z += r.z; v.w += r.w;
                }
                *optr = v;
            }
        }
    } else {
        #pragma unroll
        for (int i = 0; i < 8; i++) {
            int row = bm + ty * 8 + i;
            #pragma unroll
            for (int j = 0; j < 8; j++) {
                int col = bn + tx * 8 + j;
                if (col < N) {
                    float v = acc[i][j];
                    if (BIAS) v += bias[col];
                    if (GELU) v = gelu_tanh(v);
                    size_t o = (size_t)row * N + col;
                    if (RESID) v += C[o];
                    C[o] = v;
                }
            }
        }
    }
}

// ---------------- attention: one block per (b, h, q-row) ----------------
__global__ __launch_bounds__(128) void attention_kernel(
    const float* __restrict__ qkv, float* __restrict__ y)
{
    int q = blockIdx.x, h = blockIdx.y, b = blockIdx.z;
    int tid = threadIdx.x;

    __shared__ float sq[HD];
    __shared__ float sc[SEQ];
    __shared__ float red[4];
    __shared__ float part[128];

    const size_t rstride = 3 * EMB;
    const float* base = qkv + (size_t)b * SEQ * rstride;

    if (tid < HD) sq[tid] = base[(size_t)q * rstride + h * HD + tid];
    __syncthreads();

    int nk = q + 1;
    // scores
    for (int k = tid; k < nk; k += 128) {
        const float* kr = base + (size_t)k * rstride + EMB + h * HD;
        float s = 0.f;
        #pragma unroll
        for (int d = 0; d < HD; d += 4) {
            float4 kv = *(const float4*)(kr + d);
            s += sq[d] * kv.x + sq[d + 1] * kv.y + sq[d + 2] * kv.z + sq[d + 3] * kv.w;
        }
        sc[k] = s * 0.125f;   // 1/sqrt(64)
    }
    __syncthreads();

    // block max
    float m = -1e30f;
    for (int k = tid; k < nk; k += 128) m = fmaxf(m, sc[k]);
    #pragma unroll
    for (int o = 16; o > 0; o >>= 1) m = fmaxf(m, __shfl_xor_sync(0xffffffffu, m, o));
    if ((tid & 31) == 0) red[tid >> 5] = m;
    __syncthreads();
    m = fmaxf(fmaxf(red[0], red[1]), fmaxf(red[2], red[3]));
    __syncthreads();

    // exp + sum
    float sum = 0.f;
    for (int k = tid; k < nk; k += 128) {
        float e = __expf(sc[k] - m);
        sc[k] = e;
        sum += e;
    }
    #pragma unroll
    for (int o = 16; o > 0; o >>= 1) sum += __shfl_xor_sync(0xffffffffu, sum, o);
    if ((tid & 31) == 0) red[tid >> 5] = sum;
    __syncthreads();
    float inv = 1.0f / (red[0] + red[1] + red[2] + red[3]);

    // weighted sum over V: thread (half, d) accumulates keys half, half+2, ...
    int d = tid & 63, half = tid >> 6;
    float acc = 0.f;
    for (int k = half; k < nk; k += 2)
        acc += sc[k] * base[(size_t)k * rstride + 2 * EMB + h * HD + d];
    part[tid] = acc;
    __syncthreads();
    if (tid < HD)
        y[((size_t)(b * SEQ + q)) * EMB + h * HD + tid] = (part[tid] + part[tid + 64]) * inv;
}

// ---------------- launcher ----------------
extern "C" void kernel_launch(void* const* d_in, const int* in_sizes, int n_in,
                              void* d_out, int out_size)
{
    const int*   idx    = (const int*)  d_in[0];
    const float* wte    = (const float*)d_in[1];
    const float* wpe    = (const float*)d_in[2];
    const float* ln1_g  = (const float*)d_in[3];
    const float* ln1_b  = (const float*)d_in[4];
    const float* attn_w = (const float*)d_in[5];
    const float* attn_b = (const float*)d_in[6];
    const float* proj_w = (const float*)d_in[7];
    const float* proj_b = (const float*)d_in[8];
    const float* ln2_g  = (const float*)d_in[9];
    const float* ln2_b  = (const float*)d_in[10];
    const float* mlp_w1 = (const float*)d_in[11];
    const float* mlp_b1 = (const float*)d_in[12];
    const float* mlp_w2 = (const float*)d_in[13];
    const float* mlp_b2 = (const float*)d_in[14];
    const float* lnf_g  = (const float*)d_in[15];
    const float* lnf_b  = (const float*)d_in[16];
    const float* head_w = (const float*)d_in[17];
    float* out = (float*)d_out;

    float *x, *h, *qkv, *y, *act;
    cudaGetSymbolAddress((void**)&x,   g_x);
    cudaGetSymbolAddress((void**)&h,   g_h);
    cudaGetSymbolAddress((void**)&qkv, g_qkv);
    cudaGetSymbolAddress((void**)&y,   g_y);
    cudaGetSymbolAddress((void**)&act, g_act);

    embed_kernel<<<(MROWS * EMB + 255) / 256, 256>>>(idx, wte, wpe, x);

    for (int l = 0; l < NL; l++) {
        layernorm_kernel<<<MROWS, 256>>>(x, ln1_g + l * EMB, ln1_b + l * EMB, h);

        gemm_kernel<false, false, true><<<dim3(3 * EMB / 128, MROWS / 128), 256>>>(
            h, attn_w + (size_t)l * EMB * 3 * EMB, attn_b + l * 3 * EMB, qkv,
            MROWS, 3 * EMB, EMB);

        attention_kernel<<<dim3(SEQ, NH, BATCH), 128>>>(qkv, y);

        gemm_kernel<false, true, true><<<dim3(EMB / 128, MROWS / 128), 256>>>(
            y, proj_w + (size_t)l * EMB * EMB, proj_b + l * EMB, x,
            MROWS, EMB, EMB);

        layernorm_kernel<<<MROWS, 256>>>(x, ln2_g + l * EMB, ln2_b + l * EMB, h);

        gemm_kernel<true, false, true><<<dim3(4 * EMB / 128, MROWS / 128), 256>>>(
            h, mlp_w1 + (size_t)l * EMB * 4 * EMB, mlp_b1 + l * 4 * EMB, act,
            MROWS, 4 * EMB, EMB);

        gemm_kernel<false, true, true><<<dim3(EMB / 128, MROWS / 128), 256>>>(
            act, mlp_w2 + (size_t)l * 4 * EMB * EMB, mlp_b2 + l * EMB, x,
            MROWS, EMB, 4 * EMB);
    }

    layernorm_kernel<<<MROWS, 256>>>(x, lnf_g, lnf_b, h);

    gemm_kernel<false, false, false><<<dim3((VOCAB + 127) / 128, MROWS / 128), 256>>>(
        h, head_w, nullptr, out, MROWS, VOCAB, EMB);
}

// round 4
// speedup vs baseline: 1.2934x; 1.2934x over previous
#include <cuda_runtime.h>
#include <math.h>

// GPT-2 small forward: B=2, T=1024, E=768, H=12, hd=64, L=8, V=50257
#define BATCH 2
#define SEQ   1024
#define EMB   768
#define NH    12
#define HD    64
#define NL    8
#define VOCAB 50257
#define MROWS (BATCH*SEQ)   // 2048

// ---------------- scratch (device globals: alloc-free) ----------------
__device__ float g_x   [MROWS * EMB];        // residual stream
__device__ float g_h   [MROWS * EMB];        // layernorm output
__device__ float g_qkv [MROWS * 3 * EMB];    // qkv projection
__device__ float g_y   [MROWS * EMB];        // attention output
__device__ float g_act [MROWS * 4 * EMB];    // mlp hidden

// ---------------- embedding ----------------
__global__ void embed_kernel(const int* __restrict__ idx,
                             const float* __restrict__ wte,
                             const float* __restrict__ wpe,
                             float* __restrict__ x)
{
    int i = blockIdx.x * blockDim.x + threadIdx.x;
    if (i < MROWS * EMB) {
        int row = i / EMB;
        int e   = i - row * EMB;
        int t   = row % SEQ;
        x[i] = wte[(size_t)idx[row] * EMB + e] + wpe[(size_t)t * EMB + e];
    }
}

// ---------------- layernorm (one block per row) ----------------
__global__ __launch_bounds__(256) void layernorm_kernel(
    const float* __restrict__ x, const float* __restrict__ g,
    const float* __restrict__ b, float* __restrict__ out)
{
    int row = blockIdx.x;
    int tid = threadIdx.x;
    const float* xr = x + (size_t)row * EMB;

    float s = 0.f, ss = 0.f;
    for (int e = tid; e < EMB; e += 256) {
        float v = xr[e];
        s += v; ss += v * v;
    }
    #pragma unroll
    for (int o = 16; o > 0; o >>= 1) {
        s  += __shfl_xor_sync(0xffffffffu, s,  o);
        ss += __shfl_xor_sync(0xffffffffu, ss, o);
    }
    __shared__ float rs[8], rss[8];
    if ((tid & 31) == 0) { rs[tid >> 5] = s; rss[tid >> 5] = ss; }
    __syncthreads();
    __shared__ float smean, sinv;
    if (tid == 0) {
        float S = 0.f, SS = 0.f;
        #pragma unroll
        for (int w = 0; w < 8; w++) { S += rs[w]; SS += rss[w]; }
        float mean = S * (1.0f / EMB);
        float var  = SS * (1.0f / EMB) - mean * mean;
        smean = mean;
        sinv  = rsqrtf(var + 1e-5f);
    }
    __syncthreads();
    float mean = smean, inv = sinv;
    float* orow = out + (size_t)row * EMB;
    for (int e = tid; e < EMB; e += 256)
        orow[e] = (xr[e] - mean) * inv * g[e] + b[e];
}

// ---------------- GEMM: C = A[M,K] @ B[K,N] (+bias)(+gelu)(+resid into C) ----------------
__device__ __forceinline__ float gelu_tanh(float v) {
    float c = v + 0.044715f * v * v * v;
    return 0.5f * v * (1.0f + tanhf(0.7978845608028654f * c));
}

// 128x128 tile, BK=8, 256 threads, 8x8 register tile, 2-stage smem double buffer.
template<bool GELU, bool RESID, bool BIAS>
__global__ __launch_bounds__(256) void gemm_kernel(
    const float* __restrict__ A, const float* __restrict__ B,
    const float* __restrict__ bias, float* __restrict__ C,
    int M, int N, int K)
{
    const int BM = 128, BN = 128, BK = 8;
    __shared__ float As[2][BK][BM];
    __shared__ float Bs[2][BK][BN];

    int bm = blockIdx.y * BM, bn = blockIdx.x * BN;
    int tid = threadIdx.x;

    int arow = tid >> 1, acol = (tid & 1) * 4;
    int brow = tid >> 5, bcol = (tid & 31) * 4;

    bool nvec = ((bn + BN) <= N) && ((N & 3) == 0);

    int tx = tid & 15, ty = tid >> 4;
    float acc[8][8];
    #pragma unroll
    for (int i = 0; i < 8; i++)
        #pragma unroll
        for (int j = 0; j < 8; j++) acc[i][j] = 0.f;

    const float* Aptr = A + (size_t)(bm + arow) * K + acol;
    const float* Bptr = B + (size_t)brow * N + bn + bcol;

    float4 av = *(const float4*)(Aptr);
    float4 bv;
    if (nvec) {
        bv = *(const float4*)(Bptr);
    } else {
        bv.x = (bn + bcol + 0 < N) ? Bptr[0] : 0.f;
        bv.y = (bn + bcol + 1 < N) ? Bptr[1] : 0.f;
        bv.z = (bn + bcol + 2 < N) ? Bptr[2] : 0.f;
        bv.w = (bn + bcol + 3 < N) ? Bptr[3] : 0.f;
    }
    As[0][acol + 0][arow] = av.x;
    As[0][acol + 1][arow] = av.y;
    As[0][acol + 2][arow] = av.z;
    As[0][acol + 3][arow] = av.w;
    *(float4*)&Bs[0][brow][bcol] = bv;
    __syncthreads();

    int stage = 0;
    for (int k0 = 0; k0 < K; k0 += BK) {
        int kn = k0 + BK;
        bool more = kn < K;

        if (more) {
            av = *(const float4*)(Aptr + kn);
            const float* Bp = Bptr + (size_t)kn * N;
            if (nvec) {
                bv = *(const float4*)Bp;
            } else {
                bv.x = (bn + bcol + 0 < N) ? Bp[0] : 0.f;
                bv.y = (bn + bcol + 1 < N) ? Bp[1] : 0.f;
                bv.z = (bn + bcol + 2 < N) ? Bp[2] : 0.f;
                bv.w = (bn + bcol + 3 < N) ? Bp[3] : 0.f;
            }
        }

        #pragma unroll
        for (int kk = 0; kk < BK; kk++) {
            float4 a0 = *(const float4*)&As[stage][kk][ty * 8];
            float4 a1 = *(const float4*)&As[stage][kk][ty * 8 + 4];
            float4 b0 = *(const float4*)&Bs[stage][kk][tx * 8];
            float4 b1 = *(const float4*)&Bs[stage][kk][tx * 8 + 4];
            float a[8] = {a0.x, a0.y, a0.z, a0.w, a1.x, a1.y, a1.z, a1.w};
            float bb[8] = {b0.x, b0.y, b0.z, b0.w, b1.x, b1.y, b1.z, b1.w};
            #pragma unroll
            for (int i = 0; i < 8; i++)
                #pragma unroll
                for (int j = 0; j < 8; j++)
                    acc[i][j] = fmaf(a[i], bb[j], acc[i][j]);
        }

        if (more) {
            int ns = stage ^ 1;
            As[ns][acol + 0][arow] = av.x;
            As[ns][acol + 1][arow] = av.y;
            As[ns][acol + 2][arow] = av.z;
            As[ns][acol + 3][arow] = av.w;
            *(float4*)&Bs[ns][brow][bcol] = bv;
            __syncthreads();
            stage = ns;
        }
    }

    if (nvec) {
        #pragma unroll
        for (int i = 0; i < 8; i++) {
            int row = bm + ty * 8 + i;
            #pragma unroll
            for (int jv = 0; jv < 2; jv++) {
                int col = bn + tx * 8 + jv * 4;
                float4 v = make_float4(acc[i][jv*4+0], acc[i][jv*4+1],
                                       acc[i][jv*4+2], acc[i][jv*4+3]);
                if (BIAS) {
                    float4 bsv = *(const float4*)(bias + col);
                    v.x += bsv.x; v.y += bsv.y; v.z += bsv.z; v.w += bsv.w;
                }
                if (GELU) {
                    v.x = gelu_tanh(v.x); v.y = gelu_tanh(v.y);
                    v.z = gelu_tanh(v.z); v.w = gelu_tanh(v.w);
                }
                float4* optr = (float4*)(C + (size_t)row * N + col);
                if (RESID) {
                    float4 r = *optr;
                    v.x += r.x; v.y += r.y; v.z += r.z; v.w += r.w;
                }
                *optr = v;
            }
        }
    } else {
        #pragma unroll
        for (int i = 0; i < 8; i++) {
            int row = bm + ty * 8 + i;
            #pragma unroll
            for (int j = 0; j < 8; j++) {
                int col = bn + tx * 8 + j;
                if (col < N) {
                    float v = acc[i][j];
                    if (BIAS) v += bias[col];
                    if (GELU) v = gelu_tanh(v);
                    size_t o = (size_t)row * N + col;
                    if (RESID) v += C[o];
                    C[o] = v;
                }
            }
        }
    }
}

// ---------------- flash attention: one block per (64-q-rows, head, batch) ----------------
// 256 threads as 16x16 grid; each thread owns a 4x4 tile of S and of O.
// Per-row softmax state (m, l) is duplicated in registers across each 16-lane group.
#define BQ 64
#define BKV 64
#define TSTR 68   // smem row stride in floats (16B-aligned, breaks conflicts)

__global__ __launch_bounds__(256) void flash_attn_kernel(
    const float* __restrict__ qkv, float* __restrict__ y)
{
    extern __shared__ float sm[];
    float* Qs = sm;                      // BQ  * TSTR
    float* Ks = Qs + BQ * TSTR;          // BKV * TSTR
    float* Vs = Ks + BKV * TSTR;         // BKV * TSTR
    float* Ps = Vs + BKV * TSTR;         // BQ  * TSTR

    int qb = blockIdx.x, h = blockIdx.y, b = blockIdx.z;
    int tid = threadIdx.x;
    int tx = tid & 15, ty = tid >> 4;

    const size_t rstr = 3 * EMB;
    const float* base = qkv + (size_t)b * SEQ * rstr + h * HD;

    // loader mapping: 4 passes, each pass covers 16 rows x 64 cols (float4)
    int lrow = tid >> 4;          // 0..15
    int lcol = (tid & 15) * 4;    // 0..60

    // ---- load Q tile (scaled by 1/sqrt(hd)) ----
    #pragma unroll
    for (int p = 0; p < 4; p++) {
        int r = p * 16 + lrow;
        float4 v = *(const float4*)(base + (size_t)(qb * BQ + r) * rstr + lcol);
        v.x *= 0.125f; v.y *= 0.125f; v.z *= 0.125f; v.w *= 0.125f;
        *(float4*)&Qs[r * TSTR + lcol] = v;
    }

    float O[4][4];
    float m_i[4], l_i[4];
    #pragma unroll
    for (int i = 0; i < 4; i++) {
        m_i[i] = -1e30f; l_i[i] = 0.f;
        #pragma unroll
        for (int j = 0; j < 4; j++) O[i][j] = 0.f;
    }

    int ntiles = qb + 1;
    for (int kt = 0; kt < ntiles; kt++) {
        __syncthreads();   // previous PV (and Q store on iter 0) done before K/V overwrite

        // ---- load K, V tiles ----
        #pragma unroll
        for (int p = 0; p < 4; p++) {
            int r = p * 16 + lrow;
            size_t grow = (size_t)(kt * BKV + r) * rstr;
            *(float4*)&Ks[r * TSTR + lcol] = *(const float4*)(base + grow + EMB + lcol);
            *(float4*)&Vs[r * TSTR + lcol] = *(const float4*)(base + grow + 2 * EMB + lcol);
        }
        __syncthreads();

        // ---- S = Q @ K^T (4x4 per thread) ----
        float S_[4][4];
        #pragma unroll
        for (int i = 0; i < 4; i++)
            #pragma unroll
            for (int j = 0; j < 4; j++) S_[i][j] = 0.f;

        #pragma unroll 4
        for (int d4 = 0; d4 < 16; d4++) {
            float4 q[4], k[4];
            #pragma unroll
            for (int i = 0; i < 4; i++)
                q[i] = *(const float4*)&Qs[(ty * 4 + i) * TSTR + d4 * 4];
            #pragma unroll
            for (int j = 0; j < 4; j++)
                k[j] = *(const float4*)&Ks[(tx * 4 + j) * TSTR + d4 * 4];
            #pragma unroll
            for (int i = 0; i < 4; i++)
                #pragma unroll
                for (int j = 0; j < 4; j++)
                    S_[i][j] += q[i].x * k[j].x + q[i].y * k[j].y
                              + q[i].z * k[j].z + q[i].w * k[j].w;
        }

        // ---- causal mask on the diagonal tile ----
        if (kt == qb) {
            #pragma unroll
            for (int i = 0; i < 4; i++) {
                int r = ty * 4 + i;
                #pragma unroll
                for (int j = 0; j < 4; j++)
                    if (tx * 4 + j > r) S_[i][j] = -1e30f;
            }
        }

        // ---- online softmax update (per 16-lane row group) ----
        #pragma unroll
        for (int i = 0; i < 4; i++) {
            float rm = fmaxf(fmaxf(S_[i][0], S_[i][1]), fmaxf(S_[i][2], S_[i][3]));
            rm = fmaxf(rm, __shfl_xor_sync(0xffffffffu, rm, 8));
            rm = fmaxf(rm, __shfl_xor_sync(0xffffffffu, rm, 4));
            rm = fmaxf(rm, __shfl_xor_sync(0xffffffffu, rm, 2));
            rm = fmaxf(rm, __shfl_xor_sync(0xffffffffu, rm, 1));
            float mnew = fmaxf(m_i[i], rm);
            float p0 = __expf(S_[i][0] - mnew);
            float p1 = __expf(S_[i][1] - mnew);
            float p2 = __expf(S_[i][2] - mnew);
            float p3 = __expf(S_[i][3] - mnew);
            float rs = p0 + p1 + p2 + p3;
            rs += __shfl_xor_sync(0xffffffffu, rs, 8);
            rs += __shfl_xor_sync(0xffffffffu, rs, 4);
            rs += __shfl_xor_sync(0xffffffffu, rs, 2);
            rs += __shfl_xor_sync(0xffffffffu, rs, 1);
            float sc = __expf(m_i[i] - mnew);
            l_i[i] = l_i[i] * sc + rs;
            m_i[i] = mnew;
            O[i][0] *= sc; O[i][1] *= sc; O[i][2] *= sc; O[i][3] *= sc;
            *(float4*)&Ps[(ty * 4 + i) * TSTR + tx * 4] = make_float4(p0, p1, p2, p3);
        }
        __syncthreads();   // Ps visible to all

        // ---- O += P @ V ----
        #pragma unroll 8
        for (int k = 0; k < BKV; k++) {
            float4 v = *(const float4*)&Vs[k * TSTR + tx * 4];
            #pragma unroll
            for (int i = 0; i < 4; i++) {
                float p = Ps[(ty * 4 + i) * TSTR + k];
                O[i][0] += p * v.x; O[i][1] += p * v.y;
                O[i][2] += p * v.z; O[i][3] += p * v.w;
            }
        }
    }

    // ---- normalize and write out ----
    #pragma unroll
    for (int i = 0; i < 4; i++) {
        float inv = 1.0f / l_i[i];
        int q = qb * BQ + ty * 4 + i;
        float4 o = make_float4(O[i][0] * inv, O[i][1] * inv,
                               O[i][2] * inv, O[i][3] * inv);
        *(float4*)&y[((size_t)(b * SEQ + q)) * EMB + h * HD + tx * 4] = o;
    }
}

#define FLASH_SMEM ((2*BQ + 2*BKV) * TSTR * 4)

// ---------------- launcher ----------------
extern "C" void kernel_launch(void* const* d_in, const int* in_sizes, int n_in,
                              void* d_out, int out_size)
{
    const int*   idx    = (const int*)  d_in[0];
    const float* wte    = (const float*)d_in[1];
    const float* wpe    = (const float*)d_in[2];
    const float* ln1_g  = (const float*)d_in[3];
    const float* ln1_b  = (const float*)d_in[4];
    const float* attn_w = (const float*)d_in[5];
    const float* attn_b = (const float*)d_in[6];
    const float* proj_w = (const float*)d_in[7];
    const float* proj_b = (const float*)d_in[8];
    const float* ln2_g  = (const float*)d_in[9];
    const float* ln2_b  = (const float*)d_in[10];
    const float* mlp_w1 = (const float*)d_in[11];
    const float* mlp_b1 = (const float*)d_in[12];
    const float* mlp_w2 = (const float*)d_in[13];
    const float* mlp_b2 = (const float*)d_in[14];
    const float* lnf_g  = (const float*)d_in[15];
    const float* lnf_b  = (const float*)d_in[16];
    const float* head_w = (const float*)d_in[17];
    float* out = (float*)d_out;

    float *x, *h, *qkv, *y, *act;
    cudaGetSymbolAddress((void**)&x,   g_x);
    cudaGetSymbolAddress((void**)&h,   g_h);
    cudaGetSymbolAddress((void**)&qkv, g_qkv);
    cudaGetSymbolAddress((void**)&y,   g_y);
    cudaGetSymbolAddress((void**)&act, g_act);

    cudaFuncSetAttribute(flash_attn_kernel,
                         cudaFuncAttributeMaxDynamicSharedMemorySize, FLASH_SMEM);

    embed_kernel<<<(MROWS * EMB + 255) / 256, 256>>>(idx, wte, wpe, x);

    for (int l = 0; l < NL; l++) {
        layernorm_kernel<<<MROWS, 256>>>(x, ln1_g + l * EMB, ln1_b + l * EMB, h);

        gemm_kernel<false, false, true><<<dim3(3 * EMB / 128, MROWS / 128), 256>>>(
            h, attn_w + (size_t)l * EMB * 3 * EMB, attn_b + l * 3 * EMB, qkv,
            MROWS, 3 * EMB, EMB);

        flash_attn_kernel<<<dim3(SEQ / BQ, NH, BATCH), 256, FLASH_SMEM>>>(qkv, y);

        gemm_kernel<false, true, true><<<dim3(EMB / 128, MROWS / 128), 256>>>(
            y, proj_w + (size_t)l * EMB * EMB, proj_b + l * EMB, x,
            MROWS, EMB, EMB);

        layernorm_kernel<<<MROWS, 256>>>(x, ln2_g + l * EMB, ln2_b + l * EMB, h);

        gemm_kernel<true, false, true><<<dim3(4 * EMB / 128, MROWS / 128), 256>>>(
            h, mlp_w1 + (size_t)l * EMB * 4 * EMB, mlp_b1 + l * 4 * EMB, act,
            MROWS, 4 * EMB, EMB);

        gemm_kernel<false, true, true><<<dim3(EMB / 128, MROWS / 128), 256>>>(
            act, mlp_w2 + (size_t)l * 4 * EMB * EMB, mlp_b2 + l * EMB, x,
            MROWS, EMB, 4 * EMB);
    }

    layernorm_kernel<<<MROWS, 256>>>(x, lnf_g, lnf_b, h);

    gemm_kernel<false, false, false><<<dim3((VOCAB + 127) / 128, MROWS / 128), 256>>>(
        h, head_w, nullptr, out, MROWS, VOCAB, EMB);
}

// round 5
// speedup vs baseline: 2.3757x; 1.8369x over previous
#include <cuda_runtime.h>
#include <math.h>
#include <stdint.h>

// GPT-2 small forward: B=2, T=1024, E=768, H=12, hd=64, L=8, V=50257
#define BATCH 2
#define SEQ   1024
#define EMB   768
#define NH    12
#define HD    64
#define NL    8
#define VOCAB 50257
#define MROWS (BATCH*SEQ)   // 2048

// ---------------- scratch (device globals: alloc-free) ----------------
__device__ float g_x   [MROWS * EMB];
__device__ float g_h   [MROWS * EMB];
__device__ float g_qkv [MROWS * 3 * EMB];
__device__ float g_y   [MROWS * EMB];
__device__ float g_act [MROWS * 4 * EMB];

// ---------------- embedding ----------------
__global__ void embed_kernel(const int* __restrict__ idx,
                             const float* __restrict__ wte,
                             const float* __restrict__ wpe,
                             float* __restrict__ x)
{
    int i = blockIdx.x * blockDim.x + threadIdx.x;
    if (i < MROWS * EMB) {
        int row = i / EMB;
        int e   = i - row * EMB;
        int t   = row % SEQ;
        x[i] = wte[(size_t)idx[row] * EMB + e] + wpe[(size_t)t * EMB + e];
    }
}

// ---------------- layernorm ----------------
__global__ __launch_bounds__(256) void layernorm_kernel(
    const float* __restrict__ x, const float* __restrict__ g,
    const float* __restrict__ b, float* __restrict__ out)
{
    int row = blockIdx.x;
    int tid = threadIdx.x;
    const float* xr = x + (size_t)row * EMB;

    float s = 0.f, ss = 0.f;
    for (int e = tid; e < EMB; e += 256) {
        float v = xr[e];
        s += v; ss += v * v;
    }
    #pragma unroll
    for (int o = 16; o > 0; o >>= 1) {
        s  += __shfl_xor_sync(0xffffffffu, s,  o);
        ss += __shfl_xor_sync(0xffffffffu, ss, o);
    }
    __shared__ float rs[8], rss[8];
    if ((tid & 31) == 0) { rs[tid >> 5] = s; rss[tid >> 5] = ss; }
    __syncthreads();
    __shared__ float smean, sinv;
    if (tid == 0) {
        float S = 0.f, SS = 0.f;
        #pragma unroll
        for (int w = 0; w < 8; w++) { S += rs[w]; SS += rss[w]; }
        float mean = S * (1.0f / EMB);
        float var  = SS * (1.0f / EMB) - mean * mean;
        smean = mean;
        sinv  = rsqrtf(var + 1e-5f);
    }
    __syncthreads();
    float mean = smean, inv = sinv;
    float* orow = out + (size_t)row * EMB;
    for (int e = tid; e < EMB; e += 256)
        orow[e] = (xr[e] - mean) * inv * g[e] + b[e];
}

// ---------------- helpers ----------------
__device__ __forceinline__ float gelu_tanh(float v) {
    float c = v + 0.044715f * v * v * v;
    return 0.5f * v * (1.0f + tanhf(0.7978845608028654f * c));
}

__device__ __forceinline__ uint32_t f2tf32(float f) {
    uint32_t u;
    asm("cvt.rna.tf32.f32 %0, %1;" : "=r"(u) : "f"(f));
    return u;
}

__device__ __forceinline__ void mma_tf32(float* d, const uint32_t* a, const uint32_t* b) {
    asm volatile(
        "mma.sync.aligned.m16n8k8.row.col.f32.tf32.tf32.f32 "
        "{%0,%1,%2,%3}, {%4,%5,%6,%7}, {%8,%9}, {%0,%1,%2,%3};\n"
        : "+f"(d[0]), "+f"(d[1]), "+f"(d[2]), "+f"(d[3])
        : "r"(a[0]), "r"(a[1]), "r"(a[2]), "r"(a[3]), "r"(b[0]), "r"(b[1]));
}

// ---------------- tf32 tensor-core GEMM ----------------
// C[M,N] = A[M,K]@B[K,N] (+bias)(+gelu)(+resid). 128x128 tile, BK=16, 256 thr,
// 8 warps as 4x2, each warp 32x64 via m16n8k8 frags. Double-buffered smem.
// K must be divisible by 16; M divisible by 128.
template<bool GELU, bool RESID, bool BIAS>
__global__ __launch_bounds__(256) void gemm_tc(
    const float* __restrict__ A, const float* __restrict__ B,
    const float* __restrict__ bias, float* __restrict__ C,
    int M, int N, int K)
{
    const int BM = 128, BN = 128, BK = 16;
    __shared__ uint32_t As[2][BK][BM + 4];
    __shared__ uint32_t Bs[2][BK][BN + 4];

    int bm = blockIdx.y * BM, bn = blockIdx.x * BN;
    int tid = threadIdx.x;
    int wid = tid >> 5, lane = tid & 31;
    int warpM = wid >> 1, warpN = wid & 1;

    // vector-safe only if full N tile and N keeps rows 16B-aligned
    bool nvec = ((bn + BN) <= N) && ((N & 3) == 0);

    // A loader: 2 threads per row, 8 consecutive k each
    int arow = tid >> 1, acol = (tid & 1) * 8;
    // B loader: 16 threads per row, 8 consecutive n each
    int brow = tid >> 4, bcol = (tid & 15) * 8;

    const float* Aptr = A + (size_t)(bm + arow) * K + acol;
    const float* Bptr = B + (size_t)brow * N + bn + bcol;

    float acc[2][8][4];
    #pragma unroll
    for (int mt = 0; mt < 2; mt++)
        #pragma unroll
        for (int nt = 0; nt < 8; nt++)
            #pragma unroll
            for (int c = 0; c < 4; c++) acc[mt][nt][c] = 0.f;

    float ar[8], br[8];

    // ---- load tile 0 ----
    {
        float4 v0 = *(const float4*)(Aptr);
        float4 v1 = *(const float4*)(Aptr + 4);
        ar[0]=v0.x; ar[1]=v0.y; ar[2]=v0.z; ar[3]=v0.w;
        ar[4]=v1.x; ar[5]=v1.y; ar[6]=v1.z; ar[7]=v1.w;
        if (nvec) {
            float4 w0 = *(const float4*)(Bptr);
            float4 w1 = *(const float4*)(Bptr + 4);
            br[0]=w0.x; br[1]=w0.y; br[2]=w0.z; br[3]=w0.w;
            br[4]=w1.x; br[5]=w1.y; br[6]=w1.z; br[7]=w1.w;
        } else {
            #pragma unroll
            for (int i = 0; i < 8; i++)
                br[i] = (bn + bcol + i < N) ? Bptr[i] : 0.f;
        }
        #pragma unroll
        for (int i = 0; i < 8; i++) {
            As[0][acol + i][arow] = f2tf32(ar[i]);
            Bs[0][brow][bcol + i] = f2tf32(br[i]);
        }
    }
    __syncthreads();

    int stage = 0;
    for (int k0 = 0; k0 < K; k0 += BK) {
        int kn = k0 + BK;
        bool more = kn < K;

        // ---- prefetch next tile ----
        if (more) {
            float4 v0 = *(const float4*)(Aptr + kn);
            float4 v1 = *(const float4*)(Aptr + kn + 4);
            ar[0]=v0.x; ar[1]=v0.y; ar[2]=v0.z; ar[3]=v0.w;
            ar[4]=v1.x; ar[5]=v1.y; ar[6]=v1.z; ar[7]=v1.w;
            const float* Bp = Bptr + (size_t)kn * N;
            if (nvec) {
                float4 w0 = *(const float4*)(Bp);
                float4 w1 = *(const float4*)(Bp + 4);
                br[0]=w0.x; br[1]=w0.y; br[2]=w0.z; br[3]=w0.w;
                br[4]=w1.x; br[5]=w1.y; br[6]=w1.z; br[7]=w1.w;
            } else {
                #pragma unroll
                for (int i = 0; i < 8; i++)
                    br[i] = (bn + bcol + i < N) ? Bp[i] : 0.f;
            }
        }

        // ---- compute: two k=8 halfsteps ----
        #pragma unroll
        for (int ks = 0; ks < 2; ks++) {
            int kb = ks * 8 + (lane & 3);
            uint32_t afr[2][4];
            #pragma unroll
            for (int mt = 0; mt < 2; mt++) {
                int m = warpM * 32 + mt * 16 + (lane >> 2);
                afr[mt][0] = As[stage][kb    ][m];
                afr[mt][1] = As[stage][kb    ][m + 8];
                afr[mt][2] = As[stage][kb + 4][m];
                afr[mt][3] = As[stage][kb + 4][m + 8];
            }
            uint32_t bfr[8][2];
            #pragma unroll
            for (int nt = 0; nt < 8; nt++) {
                int n = warpN * 64 + nt * 8 + (lane >> 2);
                bfr[nt][0] = Bs[stage][kb    ][n];
                bfr[nt][1] = Bs[stage][kb + 4][n];
            }
            #pragma unroll
            for (int mt = 0; mt < 2; mt++)
                #pragma unroll
                for (int nt = 0; nt < 8; nt++)
                    mma_tf32(acc[mt][nt], afr[mt], bfr[nt]);
        }

        // ---- store prefetched tile into other stage ----
        if (more) {
            int ns = stage ^ 1;
            #pragma unroll
            for (int i = 0; i < 8; i++) {
                As[ns][acol + i][arow] = f2tf32(ar[i]);
                Bs[ns][brow][bcol + i] = f2tf32(br[i]);
            }
            __syncthreads();
            stage = ns;
        }
    }

    // ---- epilogue ----
    #pragma unroll
    for (int mt = 0; mt < 2; mt++) {
        int r0 = bm + warpM * 32 + mt * 16 + (lane >> 2);
        #pragma unroll
        for (int nt = 0; nt < 8; nt++) {
            int c0 = bn + warpN * 64 + nt * 8 + (lane & 3) * 2;
            float* cc = acc[mt][nt];
            if (nvec) {
                float2 v0 = make_float2(cc[0], cc[1]);
                float2 v1 = make_float2(cc[2], cc[3]);
                if (BIAS) {
                    float2 bb = *(const float2*)(bias + c0);
                    v0.x += bb.x; v0.y += bb.y; v1.x += bb.x; v1.y += bb.y;
                }
                if (GELU) {
                    v0.x = gelu_tanh(v0.x); v0.y = gelu_tanh(v0.y);
                    v1.x = gelu_tanh(v1.x); v1.y = gelu_tanh(v1.y);
                }
                float2* p0 = (float2*)(C + (size_t)r0 * N + c0);
                float2* p1 = (float2*)(C + (size_t)(r0 + 8) * N + c0);
                if (RESID) {
                    float2 o0 = *p0, o1 = *p1;
                    v0.x += o0.x; v0.y += o0.y; v1.x += o1.x; v1.y += o1.y;
                }
                *p0 = v0; *p1 = v1;
            } else {
                #pragma unroll
                for (int e = 0; e < 4; e++) {
                    int row = r0 + (e >> 1) * 8;
                    int col = c0 + (e & 1);
                    if (col < N) {
                        float v = cc[e];
                        if (BIAS) v += bias[col];
                        if (GELU) v = gelu_tanh(v);
                        size_t o = (size_t)row * N + col;
                        if (RESID) v += C[o];
                        C[o] = v;
                    }
                }
            }
        }
    }
}

// ---------------- flash attention ----------------
#define BQ 64
#define BKV 64
#define TSTR 68

__global__ __launch_bounds__(256) void flash_attn_kernel(
    const float* __restrict__ qkv, float* __restrict__ y)
{
    extern __shared__ float sm[];
    float* Qs = sm;
    float* Ks = Qs + BQ * TSTR;
    float* Vs = Ks + BKV * TSTR;
    float* Ps = Vs + BKV * TSTR;

    int qb = blockIdx.x, h = blockIdx.y, b = blockIdx.z;
    int tid = threadIdx.x;
    int tx = tid & 15, ty = tid >> 4;

    const size_t rstr = 3 * EMB;
    const float* base = qkv + (size_t)b * SEQ * rstr + h * HD;

    int lrow = tid >> 4;
    int lcol = (tid & 15) * 4;

    #pragma unroll
    for (int p = 0; p < 4; p++) {
        int r = p * 16 + lrow;
        float4 v = *(const float4*)(base + (size_t)(qb * BQ + r) * rstr + lcol);
        v.x *= 0.125f; v.y *= 0.125f; v.z *= 0.125f; v.w *= 0.125f;
        *(float4*)&Qs[r * TSTR + lcol] = v;
    }

    float O[4][4];
    float m_i[4], l_i[4];
    #pragma unroll
    for (int i = 0; i < 4; i++) {
        m_i[i] = -1e30f; l_i[i] = 0.f;
        #pragma unroll
        for (int j = 0; j < 4; j++) O[i][j] = 0.f;
    }

    int ntiles = qb + 1;
    for (int kt = 0; kt < ntiles; kt++) {
        __syncthreads();

        #pragma unroll
        for (int p = 0; p < 4; p++) {
            int r = p * 16 + lrow;
            size_t grow = (size_t)(kt * BKV + r) * rstr;
            *(float4*)&Ks[r * TSTR + lcol] = *(const float4*)(base + grow + EMB + lcol);
            *(float4*)&Vs[r * TSTR + lcol] = *(const float4*)(base + grow + 2 * EMB + lcol);
        }
        __syncthreads();

        float S_[4][4];
        #pragma unroll
        for (int i = 0; i < 4; i++)
            #pragma unroll
            for (int j = 0; j < 4; j++) S_[i][j] = 0.f;

        #pragma unroll 4
        for (int d4 = 0; d4 < 16; d4++) {
            float4 q[4], k[4];
            #pragma unroll
            for (int i = 0; i < 4; i++)
                q[i] = *(const float4*)&Qs[(ty * 4 + i) * TSTR + d4 * 4];
            #pragma unroll
            for (int j = 0; j < 4; j++)
                k[j] = *(const float4*)&Ks[(tx * 4 + j) * TSTR + d4 * 4];
            #pragma unroll
            for (int i = 0; i < 4; i++)
                #pragma unroll
                for (int j = 0; j < 4; j++)
                    S_[i][j] += q[i].x * k[j].x + q[i].y * k[j].y
                              + q[i].z * k[j].z + q[i].w * k[j].w;
        }

        if (kt == qb) {
            #pragma unroll
            for (int i = 0; i < 4; i++) {
                int r = ty * 4 + i;
                #pragma unroll
                for (int j = 0; j < 4; j++)
                    if (tx * 4 + j > r) S_[i][j] = -1e30f;
            }
        }

        #pragma unroll
        for (int i = 0; i < 4; i++) {
            float rm = fmaxf(fmaxf(S_[i][0], S_[i][1]), fmaxf(S_[i][2], S_[i][3]));
            rm = fmaxf(rm, __shfl_xor_sync(0xffffffffu, rm, 8));
            rm = fmaxf(rm, __shfl_xor_sync(0xffffffffu, rm, 4));
            rm = fmaxf(rm, __shfl_xor_sync(0xffffffffu, rm, 2));
            rm = fmaxf(rm, __shfl_xor_sync(0xffffffffu, rm, 1));
            float mnew = fmaxf(m_i[i], rm);
            float p0 = __expf(S_[i][0] - mnew);
            float p1 = __expf(S_[i][1] - mnew);
            float p2 = __expf(S_[i][2] - mnew);
            float p3 = __expf(S_[i][3] - mnew);
            float rs = p0 + p1 + p2 + p3;
            rs += __shfl_xor_sync(0xffffffffu, rs, 8);
            rs += __shfl_xor_sync(0xffffffffu, rs, 4);
            rs += __shfl_xor_sync(0xffffffffu, rs, 2);
            rs += __shfl_xor_sync(0xffffffffu, rs, 1);
            float sc = __expf(m_i[i] - mnew);
            l_i[i] = l_i[i] * sc + rs;
            m_i[i] = mnew;
            O[i][0] *= sc; O[i][1] *= sc; O[i][2] *= sc; O[i][3] *= sc;
            *(float4*)&Ps[(ty * 4 + i) * TSTR + tx * 4] = make_float4(p0, p1, p2, p3);
        }
        __syncthreads();

        #pragma unroll 8
        for (int k = 0; k < BKV; k++) {
            float4 v = *(const float4*)&Vs[k * TSTR + tx * 4];
            #pragma unroll
            for (int i = 0; i < 4; i++) {
                float p = Ps[(ty * 4 + i) * TSTR + k];
                O[i][0] += p * v.x; O[i][1] += p * v.y;
                O[i][2] += p * v.z; O[i][3] += p * v.w;
            }
        }
    }

    #pragma unroll
    for (int i = 0; i < 4; i++) {
        float inv = 1.0f / l_i[i];
        int q = qb * BQ + ty * 4 + i;
        float4 o = make_float4(O[i][0] * inv, O[i][1] * inv,
                               O[i][2] * inv, O[i][3] * inv);
        *(float4*)&y[((size_t)(b * SEQ + q)) * EMB + h * HD + tx * 4] = o;
    }
}

#define FLASH_SMEM ((2*BQ + 2*BKV) * TSTR * 4)

// ---------------- launcher ----------------
extern "C" void kernel_launch(void* const* d_in, const int* in_sizes, int n_in,
                              void* d_out, int out_size)
{
    const int*   idx    = (const int*)  d_in[0];
    const float* wte    = (const float*)d_in[1];
    const float* wpe    = (const float*)d_in[2];
    const float* ln1_g  = (const float*)d_in[3];
    const float* ln1_b  = (const float*)d_in[4];
    const float* attn_w = (const float*)d_in[5];
    const float* attn_b = (const float*)d_in[6];
    const float* proj_w = (const float*)d_in[7];
    const float* proj_b = (const float*)d_in[8];
    const float* ln2_g  = (const float*)d_in[9];
    const float* ln2_b  = (const float*)d_in[10];
    const float* mlp_w1 = (const float*)d_in[11];
    const float* mlp_b1 = (const float*)d_in[12];
    const float* mlp_w2 = (const float*)d_in[13];
    const float* mlp_b2 = (const float*)d_in[14];
    const float* lnf_g  = (const float*)d_in[15];
    const float* lnf_b  = (const float*)d_in[16];
    const float* head_w = (const float*)d_in[17];
    float* out = (float*)d_out;

    float *x, *h, *qkv, *y, *act;
    cudaGetSymbolAddress((void**)&x,   g_x);
    cudaGetSymbolAddress((void**)&h,   g_h);
    cudaGetSymbolAddress((void**)&qkv, g_qkv);
    cudaGetSymbolAddress((void**)&y,   g_y);
    cudaGetSymbolAddress((void**)&act, g_act);

    cudaFuncSetAttribute(flash_attn_kernel,
                         cudaFuncAttributeMaxDynamicSharedMemorySize, FLASH_SMEM);

    embed_kernel<<<(MROWS * EMB + 255) / 256, 256>>>(idx, wte, wpe, x);

    for (int l = 0; l < NL; l++) {
        layernorm_kernel<<<MROWS, 256>>>(x, ln1_g + l * EMB, ln1_b + l * EMB, h);

        gemm_tc<false, false, true><<<dim3(3 * EMB / 128, MROWS / 128), 256>>>(
            h, attn_w + (size_t)l * EMB * 3 * EMB, attn_b + l * 3 * EMB, qkv,
            MROWS, 3 * EMB, EMB);

        flash_attn_kernel<<<dim3(SEQ / BQ, NH, BATCH), 256, FLASH_SMEM>>>(qkv, y);

        gemm_tc<false, true, true><<<dim3(EMB / 128, MROWS / 128), 256>>>(
            y, proj_w + (size_t)l * EMB * EMB, proj_b + l * EMB, x,
            MROWS, EMB, EMB);

        layernorm_kernel<<<MROWS, 256>>>(x, ln2_g + l * EMB, ln2_b + l * EMB, h);

        gemm_tc<true, false, true><<<dim3(4 * EMB / 128, MROWS / 128), 256>>>(
            h, mlp_w1 + (size_t)l * EMB * 4 * EMB, mlp_b1 + l * 4 * EMB, act,
            MROWS, 4 * EMB, EMB);

        gemm_tc<false, true, true><<<dim3(EMB / 128, MROWS / 128), 256>>>(
            act, mlp_w2 + (size_t)l * 4 * EMB * EMB, mlp_b2 + l * EMB, x,
            MROWS, EMB, 4 * EMB);
    }

    layernorm_kernel<<<MROWS, 256>>>(x, lnf_g, lnf_b, h);

    gemm_tc<false, false, false><<<dim3((VOCAB + 127) / 128, MROWS / 128), 256>>>(
        h, head_w, nullptr, out, MROWS, VOCAB, EMB);
}